// round 1
// baseline (speedup 1.0000x reference)
#include <cuda_runtime.h>
#include <math.h>

#define DD   128
#define NBR  30
#define NQ   4096
#define FEWN 5
#define H2   256
#define H4   512
#define NG   2048
#define RQ   (NQ*NBR)
#define RS   (FEWN*NBR)
#define R_TOT (2*RQ + 2*RS)

// ---------------- scratch (static device globals; no allocation) ----------------
__device__ float g_logits[2*R_TOT];
__device__ float g_query[2*NQ*H2];
__device__ float g_support[2*FEWN*H2];
__device__ float g_qg[NQ*H2];
__device__ float g_sg[FEWN*H2];
__device__ float g_h1[NQ*H4];
__device__ float g_z[NQ*H2];
__device__ float g_sh1[FEWN*H4];
__device__ float g_sz[FEWN*H2];
__device__ float g_Gx[(size_t)NQ*NG];
__device__ float g_Ds[(size_t)NQ*NG];
__device__ float g_SW[FEWN*NG];
__device__ float g_smean[H2];
__device__ float g_c[NQ*H4];
__device__ float g_h[NQ*H2];
__device__ float g_attn[NQ*FEWN];
__device__ float g_bsum[NG];

__device__ __forceinline__ float sigm(float x) { return 1.f/(1.f+expf(-x)); }

// ---------------- generic fp32 TN GEMM: C = A[M,K] * W[N,K]^T (+bias/epi) ------
#define BM 128
#define BN 128
#define BK 16

__global__ __launch_bounds__(256) void sgemm_tn(
    int M, int N, int K,
    const float* __restrict__ A, int lda,
    const float* __restrict__ W, int ldw,
    const float* __restrict__ bias,
    float* __restrict__ C, int ldc,
    int epi, const float* __restrict__ res, int ldres)
{
    __shared__ float As[BK][BM+4];
    __shared__ float Bs[BK][BN+4];
    const int tid = threadIdx.x;
    const int tx = tid & 15, ty = tid >> 4;
    const int bm = blockIdx.x * BM, bn = blockIdx.y * BN;

    float acc[8][8];
    #pragma unroll
    for (int i = 0; i < 8; i++)
        #pragma unroll
        for (int j = 0; j < 8; j++) acc[i][j] = 0.f;

    for (int k0 = 0; k0 < K; k0 += BK) {
        #pragma unroll
        for (int l = 0; l < 2; l++) {
            int idx = tid + l*256;
            int row = idx >> 2, kq = (idx & 3) << 2;
            float4 v = make_float4(0.f,0.f,0.f,0.f);
            if (bm + row < M) v = *(const float4*)(A + (size_t)(bm+row)*lda + k0 + kq);
            As[kq+0][row]=v.x; As[kq+1][row]=v.y; As[kq+2][row]=v.z; As[kq+3][row]=v.w;
        }
        #pragma unroll
        for (int l = 0; l < 2; l++) {
            int idx = tid + l*256;
            int row = idx >> 2, kq = (idx & 3) << 2;
            float4 v = *(const float4*)(W + (size_t)(bn+row)*ldw + k0 + kq);
            Bs[kq+0][row]=v.x; Bs[kq+1][row]=v.y; Bs[kq+2][row]=v.z; Bs[kq+3][row]=v.w;
        }
        __syncthreads();
        #pragma unroll
        for (int k = 0; k < BK; k++) {
            float a[8], b[8];
            #pragma unroll
            for (int i = 0; i < 8; i++) a[i] = As[k][ty*8+i];
            #pragma unroll
            for (int j = 0; j < 8; j++) b[j] = Bs[k][tx*8+j];
            #pragma unroll
            for (int i = 0; i < 8; i++)
                #pragma unroll
                for (int j = 0; j < 8; j++) acc[i][j] += a[i]*b[j];
        }
        __syncthreads();
    }
    #pragma unroll
    for (int i = 0; i < 8; i++) {
        int row = bm + ty*8 + i;
        if (row >= M) continue;
        #pragma unroll
        for (int j = 0; j < 8; j++) {
            int col = bn + tx*8 + j;
            float v = acc[i][j];
            if (bias) v += bias[col];
            if (epi == 1) v = fmaxf(v, 0.f);
            else if (epi == 2) v += res[(size_t)row*ldres + col];
            C[(size_t)row*ldc + col] = v;
        }
    }
}

// ---------------- neighbor attention logits (gathered GEMM + tanh/dot epi) -----
__global__ __launch_bounds__(256) void neigh_logit_kernel(
    const float* __restrict__ emb, const float* __restrict__ embv,
    const float* __restrict__ nW,  const float* __restrict__ nWb,
    const float* __restrict__ nu,  const float* __restrict__ nub,
    const float* __restrict__ nvW, const float* __restrict__ nvWb,
    const float* __restrict__ nvu, const float* __restrict__ nvub,
    const int* __restrict__ ql, const int* __restrict__ qr,
    const int* __restrict__ sl, const int* __restrict__ sr)
{
    const int path = blockIdx.y;
    const float* tab = path ? embv : emb;
    const float* Wt  = path ? nvW  : nW;
    const float* Wb  = path ? nvWb : nWb;
    const float* uu  = path ? nvu  : nu;
    const float  ub  = path ? nvub[0] : nub[0];

    __shared__ int relS[BM], entS[BM];
    __shared__ float As[BK][BM+4];
    __shared__ float Bs[BK][BN+4];
    const int tid = threadIdx.x;
    const int bm = blockIdx.x * BM;

    if (tid < BM) {
        int r = bm + tid;
        int rel = 0, ent = 0;
        if (r < R_TOT) {
            const int* conn; int local;
            if (r < RQ)            { conn = ql; local = r; }
            else if (r < 2*RQ)     { conn = qr; local = r - RQ; }
            else if (r < 2*RQ+RS)  { conn = sl; local = r - 2*RQ; }
            else                   { conn = sr; local = r - 2*RQ - RS; }
            rel = conn[local*2]; ent = conn[local*2+1];
        }
        relS[tid] = rel; entS[tid] = ent;
    }
    __syncthreads();

    const int tx = tid & 15, ty = tid >> 4;
    float acc[8][8];
    #pragma unroll
    for (int i = 0; i < 8; i++)
        #pragma unroll
        for (int j = 0; j < 8; j++) acc[i][j] = 0.f;

    for (int k0 = 0; k0 < 2*DD; k0 += BK) {
        const int half = (k0 >= DD);
        const int kk = k0 & (DD-1);
        #pragma unroll
        for (int l = 0; l < 2; l++) {
            int idx = tid + l*256;
            int row = idx >> 2, kq = (idx & 3) << 2;
            int sym = half ? entS[row] : relS[row];
            float4 v = *(const float4*)(tab + (size_t)sym*DD + kk + kq);
            As[kq+0][row]=v.x; As[kq+1][row]=v.y; As[kq+2][row]=v.z; As[kq+3][row]=v.w;
        }
        #pragma unroll
        for (int l = 0; l < 2; l++) {
            int idx = tid + l*256;
            int row = idx >> 2, kq = (idx & 3) << 2;
            float4 v = *(const float4*)(Wt + (size_t)row*(2*DD) + k0 + kq);
            Bs[kq+0][row]=v.x; Bs[kq+1][row]=v.y; Bs[kq+2][row]=v.z; Bs[kq+3][row]=v.w;
        }
        __syncthreads();
        #pragma unroll
        for (int k = 0; k < BK; k++) {
            float a[8], b[8];
            #pragma unroll
            for (int i = 0; i < 8; i++) a[i] = As[k][ty*8+i];
            #pragma unroll
            for (int j = 0; j < 8; j++) b[j] = Bs[k][tx*8+j];
            #pragma unroll
            for (int i = 0; i < 8; i++)
                #pragma unroll
                for (int j = 0; j < 8; j++) acc[i][j] += a[i]*b[j];
        }
        __syncthreads();
    }
    // logit = nub + sum_j nu[j]*tanh(hid_j + nWb[j]); reduce 128 cols across 16 lanes
    #pragma unroll
    for (int i = 0; i < 8; i++) {
        float part = 0.f;
        #pragma unroll
        for (int j = 0; j < 8; j++) {
            int col = tx*8 + j;
            part += uu[col] * tanhf(acc[i][j] + Wb[col]);
        }
        part += __shfl_xor_sync(0xffffffffu, part, 8);
        part += __shfl_xor_sync(0xffffffffu, part, 4);
        part += __shfl_xor_sync(0xffffffffu, part, 2);
        part += __shfl_xor_sync(0xffffffffu, part, 1);
        int row = bm + ty*8 + i;
        if (tx == 0 && row < R_TOT) g_logits[path*R_TOT + row] = part + ub;
    }
}

// ---------------- softmax over 30 neighbors + weighted pool + tanh -------------
__global__ __launch_bounds__(128) void pool_kernel(
    const float* __restrict__ emb,
    const int* __restrict__ ql, const int* __restrict__ qr,
    const int* __restrict__ sl, const int* __restrict__ sr)
{
    const int gs = blockIdx.x;
    const int tid = threadIdx.x;
    __shared__ float att[2][NBR];
    __shared__ int entS[NBR];
    int set, local;
    if (gs < NQ)            { set=0; local=gs; }
    else if (gs < 2*NQ)     { set=1; local=gs-NQ; }
    else if (gs < 2*NQ+FEWN){ set=2; local=gs-2*NQ; }
    else                    { set=3; local=gs-2*NQ-FEWN; }
    const int rowbase = (set==0?0: set==1?RQ : set==2?2*RQ : 2*RQ+RS) + local*NBR;
    const int* conn = set==0?ql : set==1?qr : set==2?sl : sr;
    const int warp = tid >> 5, lane = tid & 31;

    if (warp == 0 && lane < NBR) entS[lane] = conn[(local*NBR+lane)*2+1];
    if (warp < 2) {
        float v = (lane < NBR) ? g_logits[warp*R_TOT + rowbase + lane] : -1e30f;
        float m = v;
        #pragma unroll
        for (int o = 16; o; o >>= 1) m = fmaxf(m, __shfl_xor_sync(~0u, m, o));
        float e = (lane < NBR) ? expf(v - m) : 0.f;
        float s = e;
        #pragma unroll
        for (int o = 16; o; o >>= 1) s += __shfl_xor_sync(~0u, s, o);
        if (lane < NBR) att[warp][lane] = e / s;
    }
    __syncthreads();
    const int d = tid;  // 0..127
    float a0 = 0.f, a1 = 0.f;
    #pragma unroll 6
    for (int nb = 0; nb < NBR; nb++) {
        float ev = emb[(size_t)entS[nb]*DD + d];
        a0 += att[0][nb]*ev;
        a1 += att[1][nb]*ev;
    }
    float t0 = tanhf(a0), t1 = tanhf(a1);
    if (set < 2) {
        g_query[0*(size_t)NQ*H2 + (size_t)local*H2 + set*DD + d] = t0;
        g_query[1*(size_t)NQ*H2 + (size_t)local*H2 + set*DD + d] = t1;
    } else {
        int s2 = set - 2;
        g_support[0*FEWN*H2 + local*H2 + s2*DD + d] = t0;
        g_support[1*FEWN*H2 + local*H2 + s2*DD + d] = t1;
    }
}

// ---------------- layernorm (ddof=1, eps added to sigma) -----------------------
__global__ __launch_bounds__(256) void ln_kernel(
    const float* __restrict__ Z, float* __restrict__ O,
    const float* __restrict__ ga, const float* __restrict__ gb)
{
    const int row = blockIdx.x, c = threadIdx.x;
    float z = Z[(size_t)row*H2 + c];
    __shared__ float s1[H2], s2[H2];
    s1[c] = z; s2[c] = z*z;
    __syncthreads();
    for (int o = 128; o; o >>= 1) {
        if (c < o) { s1[c] += s1[c+o]; s2[c] += s2[c+o]; }
        __syncthreads();
    }
    float mu  = s1[0] * (1.f/H2);
    float var = (s2[0] - (float)H2*mu*mu) * (1.f/(H2-1));
    float sig = sqrtf(fmaxf(var, 0.f));
    O[(size_t)row*H2 + c] = (z - mu)/(sig + 1e-3f)*ga[c] + gb[c];
}

__global__ void smean_kernel() {
    int c = threadIdx.x;
    float s = 0.f;
    #pragma unroll
    for (int f = 0; f < FEWN; f++) s += g_sg[f*H2 + c];
    g_smean[c] = s * (1.f/FEWN);
}

__global__ void bsum_kernel(const float* __restrict__ bih, const float* __restrict__ bhh) {
    int i = blockIdx.x*blockDim.x + threadIdx.x;
    if (i < NG) g_bsum[i] = bih[i] + bhh[i];
}

// ---------------- LSTM elementwise step (+ rank-5 attn@SW fold) ----------------
__global__ __launch_bounds__(256) void lstm_ew_kernel(int t)
{
    int idx = blockIdx.x*256 + threadIdx.x;      // 0 .. NQ*H4-1
    int r = idx >> 9, u = idx & 511;
    size_t base = (size_t)r*NG;
    float gi = g_Gx[base+u],      gf = g_Gx[base+512+u];
    float gg = g_Gx[base+1024+u], go = g_Gx[base+1536+u];
    float cprev = 0.f;
    if (t > 0) {
        gi += g_Ds[base+u];      gf += g_Ds[base+512+u];
        gg += g_Ds[base+1024+u]; go += g_Ds[base+1536+u];
        #pragma unroll
        for (int f = 0; f < FEWN; f++) {
            float a = g_attn[r*FEWN + f];
            gi += a*g_SW[f*NG + u];
            gf += a*g_SW[f*NG + 512 + u];
            gg += a*g_SW[f*NG + 1024 + u];
            go += a*g_SW[f*NG + 1536 + u];
        }
        cprev = g_c[(size_t)r*H4 + u];
    }
    float cn = sigm(gf)*cprev + sigm(gi)*tanhf(gg);
    g_c[(size_t)r*H4 + u] = cn;
    if (u < H2) {
        float ho = sigm(go)*tanhf(cn);
        g_h[(size_t)r*H2 + u] = g_qg[(size_t)r*H2 + u] + ho;
    }
}

// ---------------- attention over 5 support rows --------------------------------
__global__ __launch_bounds__(128) void attn_kernel()
{
    int r = blockIdx.x*4 + (threadIdx.x >> 5);
    int lane = threadIdx.x & 31;
    float sc[FEWN];
    #pragma unroll
    for (int f = 0; f < FEWN; f++) {
        float p = 0.f;
        for (int c = lane; c < H2; c += 32) p += g_h[(size_t)r*H2 + c]*g_sg[f*H2 + c];
        #pragma unroll
        for (int o = 16; o; o >>= 1) p += __shfl_xor_sync(~0u, p, o);
        sc[f] = p;
    }
    float m = sc[0];
    #pragma unroll
    for (int f = 1; f < FEWN; f++) m = fmaxf(m, sc[f]);
    float e[FEWN], s = 0.f;
    #pragma unroll
    for (int f = 0; f < FEWN; f++) { e[f] = expf(sc[f]-m); s += e[f]; }
    if (lane < FEWN) g_attn[r*FEWN + lane] = e[lane]/s;
}

__global__ __launch_bounds__(128) void score_kernel(float* __restrict__ out, int path)
{
    int r = blockIdx.x*4 + (threadIdx.x >> 5);
    int lane = threadIdx.x & 31;
    float p = 0.f;
    for (int c = lane; c < H2; c += 32) p += g_h[(size_t)r*H2 + c]*g_smean[c];
    #pragma unroll
    for (int o = 16; o; o >>= 1) p += __shfl_xor_sync(~0u, p, o);
    if (lane == 0) out[path*NQ + r] = p;
}

// ---------------- host orchestration -------------------------------------------
extern "C" void kernel_launch(void* const* d_in, const int* in_sizes, int n_in,
                              void* d_out, int out_size)
{
    (void)in_sizes; (void)n_in; (void)out_size;
    const float* emb   = (const float*)d_in[0];
    const float* embv  = (const float*)d_in[1];
    const float* nW    = (const float*)d_in[2];
    const float* nWb   = (const float*)d_in[3];
    const float* nu    = (const float*)d_in[4];
    const float* nub   = (const float*)d_in[5];
    const float* nvW   = (const float*)d_in[6];
    const float* nvWb  = (const float*)d_in[7];
    const float* nvu   = (const float*)d_in[8];
    const float* nvub  = (const float*)d_in[9];
    const float* p1W   = (const float*)d_in[10];
    const float* p1b   = (const float*)d_in[11];
    const float* p2W   = (const float*)d_in[12];
    const float* p2b   = (const float*)d_in[13];
    const float* ln_a  = (const float*)d_in[14];
    const float* ln_b  = (const float*)d_in[15];
    const float* Wih   = (const float*)d_in[16];
    const float* Whh   = (const float*)d_in[17];
    const float* bih   = (const float*)d_in[18];
    const float* bhh   = (const float*)d_in[19];
    const int* ql = (const int*)d_in[20];
    const int* qr = (const int*)d_in[21];
    const int* sl = (const int*)d_in[22];
    const int* sr = (const int*)d_in[23];
    float* out = (float*)d_out;

    float *p_query, *p_support, *p_qg, *p_sg, *p_h1, *p_z, *p_sh1, *p_sz,
          *p_Gx, *p_Ds, *p_SW, *p_h, *p_bsum;
    cudaGetSymbolAddress((void**)&p_query,   g_query);
    cudaGetSymbolAddress((void**)&p_support, g_support);
    cudaGetSymbolAddress((void**)&p_qg,      g_qg);
    cudaGetSymbolAddress((void**)&p_sg,      g_sg);
    cudaGetSymbolAddress((void**)&p_h1,      g_h1);
    cudaGetSymbolAddress((void**)&p_z,       g_z);
    cudaGetSymbolAddress((void**)&p_sh1,     g_sh1);
    cudaGetSymbolAddress((void**)&p_sz,      g_sz);
    cudaGetSymbolAddress((void**)&p_Gx,      g_Gx);
    cudaGetSymbolAddress((void**)&p_Ds,      g_Ds);
    cudaGetSymbolAddress((void**)&p_SW,      g_SW);
    cudaGetSymbolAddress((void**)&p_h,       g_h);
    cudaGetSymbolAddress((void**)&p_bsum,    g_bsum);

    bsum_kernel<<<(NG+255)/256, 256>>>(bih, bhh);

    dim3 gN((R_TOT + BM - 1)/BM, 2);
    neigh_logit_kernel<<<gN, 256>>>(emb, embv, nW, nWb, nu, nub,
                                    nvW, nvWb, nvu, nvub, ql, qr, sl, sr);
    pool_kernel<<<2*NQ + 2*FEWN, 128>>>(emb, ql, qr, sl, sr);

    for (int p = 0; p < 2; p++) {
        const float* sup = p_support + (size_t)p*FEWN*H2;
        const float* qry = p_query   + (size_t)p*NQ*H2;

        // support encoder on support [5,256]
        sgemm_tn<<<dim3(1, 512/BN), 256>>>(FEWN, 512, 256, sup, 256, p1W, 256, p1b,
                                           p_sh1, 512, 1, nullptr, 0);
        sgemm_tn<<<dim3(1, 256/BN), 256>>>(FEWN, 256, 512, p_sh1, 512, p2W, 512, p2b,
                                           p_sz, 256, 2, sup, 256);
        ln_kernel<<<FEWN, 256>>>(p_sz, p_sg, ln_a, ln_b);

        // support encoder on query [4096,256]
        sgemm_tn<<<dim3(NQ/BM, 512/BN), 256>>>(NQ, 512, 256, qry, 256, p1W, 256, p1b,
                                               p_h1, 512, 1, nullptr, 0);
        sgemm_tn<<<dim3(NQ/BM, 256/BN), 256>>>(NQ, 256, 512, p_h1, 512, p2W, 512, p2b,
                                               p_z, 256, 2, qry, 256);
        ln_kernel<<<NQ, 256>>>(p_z, p_qg, ln_a, ln_b);

        // SW = s_g @ WhhB^T ; s_mean
        sgemm_tn<<<dim3(1, NG/BN), 256>>>(FEWN, NG, 256, p_sg, 256, Whh + 256, 512,
                                          nullptr, p_SW, NG, 0, nullptr, 0);
        smean_kernel<<<1, 256>>>();

        // G_x = q_g @ Wih^T + (bih+bhh)
        sgemm_tn<<<dim3(NQ/BM, NG/BN), 256>>>(NQ, NG, 256, p_qg, 256, Wih, 256,
                                              p_bsum, p_Gx, NG, 0, nullptr, 0);

        // LSTM steps
        lstm_ew_kernel<<<NQ*H4/256, 256>>>(0);
        attn_kernel<<<NQ/4, 128>>>();
        for (int t = 1; t < 4; t++) {
            sgemm_tn<<<dim3(NQ/BM, NG/BN), 256>>>(NQ, NG, 256, p_h, 256, Whh, 512,
                                                  nullptr, p_Ds, NG, 0, nullptr, 0);
            lstm_ew_kernel<<<NQ*H4/256, 256>>>(t);
            if (t < 3) attn_kernel<<<NQ/4, 128>>>();
        }
        score_kernel<<<NQ/4, 128>>>(out, p);
    }
}

// round 3
// speedup vs baseline: 1.2108x; 1.2108x over previous
#include <cuda_runtime.h>
#include <math.h>
#include <stdint.h>

#define DD   128
#define NBR  30
#define NQ   4096
#define FEWN 5
#define H2   256
#define H4   512
#define NG   2048
#define RQ   (NQ*NBR)
#define RS   (FEWN*NBR)
#define R_TOT (2*RQ + 2*RS)
#define MB   (2*NQ)          // merged batch = 8192 (path-major)

// ---------------- scratch (static device globals; no allocation) ----------------
__device__ float g_logits[2*R_TOT];
__device__ float g_query[MB*H2];          // [path*NQ + b][256]
__device__ float g_support[2*FEWN*H2];    // [path*5 + f][256]
__device__ float g_qg[MB*H2];
__device__ float g_sg[2*FEWN*H2];
__device__ float g_h1[(size_t)MB*H4];
__device__ float g_z[MB*H2];
__device__ float g_sh1[2*FEWN*H4];
__device__ float g_sz[2*FEWN*H2];
__device__ float g_Gx[(size_t)MB*NG];
__device__ float g_Ds[(size_t)MB*NG];
__device__ float g_SW[2*FEWN*NG];
__device__ float g_smean[2*H2];
__device__ float g_c[(size_t)MB*H4];
__device__ float g_h[MB*H2];
__device__ float g_attn[MB*FEWN];
__device__ float g_bsum[NG];

__device__ __forceinline__ float sigm(float x) { return 1.f/(1.f+expf(-x)); }

// ---------------- tf32 helpers --------------------------------------------------
__device__ __forceinline__ uint32_t tf32_rna(float x) {
    uint32_t u; asm("cvt.rna.tf32.f32 %0, %1;" : "=r"(u) : "f"(x)); return u;
}
__device__ __forceinline__ void split2(float x, float& hi, float& lo) {
    hi = __uint_as_float(tf32_rna(x));
    lo = __uint_as_float(tf32_rna(x - hi));
}
__device__ __forceinline__ void mma8(float* c, const uint32_t* a, const uint32_t* b) {
    asm volatile("mma.sync.aligned.m16n8k8.row.col.f32.tf32.tf32.f32 "
        "{%0,%1,%2,%3}, {%4,%5,%6,%7}, {%8,%9}, {%0,%1,%2,%3};"
        : "+f"(c[0]), "+f"(c[1]), "+f"(c[2]), "+f"(c[3])
        : "r"(a[0]), "r"(a[1]), "r"(a[2]), "r"(a[3]), "r"(b[0]), "r"(b[1]));
}

#define TBM 128
#define TBN 128
#define TBK 16
#define TLD (TBM + 8)

// ---------------- TF32x2 TN GEMM: C = A[M,K] * W[N,K]^T (+bias/epi) -------------
// epi: 0=none, 1=relu, 2=+res
__global__ __launch_bounds__(256) void tgemm_tn(
    int M, int N, int K,
    const float* __restrict__ A, int lda,
    const float* __restrict__ W, int ldw,
    const float* __restrict__ bias,
    float* __restrict__ C, int ldc,
    int epi, const float* __restrict__ res, int ldres)
{
    __shared__ float Ah[TBK][TLD], Al[TBK][TLD], Bh[TBK][TLD], Bl[TBK][TLD];
    const int tid = threadIdx.x;
    const int bm = blockIdx.x * TBM, bn = blockIdx.y * TBN;
    const int lane = tid & 31, wid = tid >> 5;
    const int wm = wid >> 2, wn = wid & 3;   // warp tile (64 x 32)

    float acc[4][4][4];
    #pragma unroll
    for (int i = 0; i < 4; i++)
        #pragma unroll
        for (int j = 0; j < 4; j++)
            #pragma unroll
            for (int l = 0; l < 4; l++) acc[i][j][l] = 0.f;

    for (int k0 = 0; k0 < K; k0 += TBK) {
        #pragma unroll
        for (int l = 0; l < 2; l++) {
            int q = tid + l * 256;              // float4 index 0..511
            int row = q >> 2, kc = (q & 3) << 2;
            float4 v = make_float4(0.f, 0.f, 0.f, 0.f);
            if (bm + row < M) v = *(const float4*)(A + (size_t)(bm + row) * lda + k0 + kc);
            float h, lo;
            split2(v.x, h, lo); Ah[kc+0][row] = h; Al[kc+0][row] = lo;
            split2(v.y, h, lo); Ah[kc+1][row] = h; Al[kc+1][row] = lo;
            split2(v.z, h, lo); Ah[kc+2][row] = h; Al[kc+2][row] = lo;
            split2(v.w, h, lo); Ah[kc+3][row] = h; Al[kc+3][row] = lo;
        }
        #pragma unroll
        for (int l = 0; l < 2; l++) {
            int q = tid + l * 256;
            int row = q >> 2, kc = (q & 3) << 2;
            float4 v = *(const float4*)(W + (size_t)(bn + row) * ldw + k0 + kc);
            float h, lo;
            split2(v.x, h, lo); Bh[kc+0][row] = h; Bl[kc+0][row] = lo;
            split2(v.y, h, lo); Bh[kc+1][row] = h; Bl[kc+1][row] = lo;
            split2(v.z, h, lo); Bh[kc+2][row] = h; Bl[kc+2][row] = lo;
            split2(v.w, h, lo); Bh[kc+3][row] = h; Bl[kc+3][row] = lo;
        }
        __syncthreads();
        #pragma unroll
        for (int k8 = 0; k8 < 2; k8++) {
            const int kk = k8 * 8 + (lane & 3);
            uint32_t ah[4][4], al[4][4], bh[4][2], bl[4][2];
            #pragma unroll
            for (int mt = 0; mt < 4; mt++) {
                int m0 = wm * 64 + mt * 16 + (lane >> 2);
                ah[mt][0] = __float_as_uint(Ah[kk][m0]);
                ah[mt][1] = __float_as_uint(Ah[kk][m0+8]);
                ah[mt][2] = __float_as_uint(Ah[kk+4][m0]);
                ah[mt][3] = __float_as_uint(Ah[kk+4][m0+8]);
                al[mt][0] = __float_as_uint(Al[kk][m0]);
                al[mt][1] = __float_as_uint(Al[kk][m0+8]);
                al[mt][2] = __float_as_uint(Al[kk+4][m0]);
                al[mt][3] = __float_as_uint(Al[kk+4][m0+8]);
            }
            #pragma unroll
            for (int nt = 0; nt < 4; nt++) {
                int n0 = wn * 32 + nt * 8 + (lane >> 2);
                bh[nt][0] = __float_as_uint(Bh[kk][n0]);
                bh[nt][1] = __float_as_uint(Bh[kk+4][n0]);
                bl[nt][0] = __float_as_uint(Bl[kk][n0]);
                bl[nt][1] = __float_as_uint(Bl[kk+4][n0]);
            }
            #pragma unroll
            for (int mt = 0; mt < 4; mt++)
                #pragma unroll
                for (int nt = 0; nt < 4; nt++) {
                    mma8(acc[mt][nt], ah[mt], bh[nt]);
                    mma8(acc[mt][nt], ah[mt], bl[nt]);
                    mma8(acc[mt][nt], al[mt], bh[nt]);
                }
        }
        __syncthreads();
    }
    #pragma unroll
    for (int mt = 0; mt < 4; mt++) {
        int r0 = bm + wm * 64 + mt * 16 + (lane >> 2);
        #pragma unroll
        for (int nt = 0; nt < 4; nt++) {
            int c0 = bn + wn * 32 + nt * 8 + ((lane & 3) << 1);
            #pragma unroll
            for (int half = 0; half < 2; half++) {
                int row = r0 + half * 8;
                if (row >= M) continue;
                #pragma unroll
                for (int jj = 0; jj < 2; jj++) {
                    int col = c0 + jj;
                    float v = acc[mt][nt][half * 2 + jj];
                    if (bias) v += bias[col];
                    if (epi == 1) v = fmaxf(v, 0.f);
                    else if (epi == 2) v += res[(size_t)row * ldres + col];
                    C[(size_t)row * ldc + col] = v;
                }
            }
        }
    }
}

// ---------------- neighbor logits: gathered TF32x2 GEMM + tanh/dot epi ----------
__global__ __launch_bounds__(256) void neigh_logit_tc(
    const float* __restrict__ emb, const float* __restrict__ embv,
    const float* __restrict__ nW,  const float* __restrict__ nWb,
    const float* __restrict__ nu,  const float* __restrict__ nub,
    const float* __restrict__ nvW, const float* __restrict__ nvWb,
    const float* __restrict__ nvu, const float* __restrict__ nvub,
    const int* __restrict__ ql, const int* __restrict__ qr,
    const int* __restrict__ sl, const int* __restrict__ sr)
{
    const int path = blockIdx.y;
    const float* tab = path ? embv : emb;
    const float* Wt  = path ? nvW  : nW;
    const float* Wb  = path ? nvWb : nWb;
    const float* uu  = path ? nvu  : nu;
    const float  ub  = path ? nvub[0] : nub[0];

    __shared__ float Ah[TBK][TLD], Al[TBK][TLD], Bh[TBK][TLD], Bl[TBK][TLD];
    __shared__ int relS[TBM], entS[TBM];
    __shared__ float sU[128], sB[128];
    __shared__ float sred[4][128];

    const int tid = threadIdx.x;
    const int bm = blockIdx.x * TBM;
    const int lane = tid & 31, wid = tid >> 5;
    const int wm = wid >> 2, wn = wid & 3;

    if (tid < TBM) {
        int r = bm + tid;
        int rel = 0, ent = 0;
        if (r < R_TOT) {
            const int* conn; int local;
            if (r < RQ)            { conn = ql; local = r; }
            else if (r < 2*RQ)     { conn = qr; local = r - RQ; }
            else if (r < 2*RQ+RS)  { conn = sl; local = r - 2*RQ; }
            else                   { conn = sr; local = r - 2*RQ - RS; }
            rel = conn[local*2]; ent = conn[local*2+1];
        }
        relS[tid] = rel; entS[tid] = ent;
    }
    if (tid < 128) { sU[tid] = uu[tid]; sB[tid] = Wb[tid]; }
    __syncthreads();

    float acc[4][4][4];
    #pragma unroll
    for (int i = 0; i < 4; i++)
        #pragma unroll
        for (int j = 0; j < 4; j++)
            #pragma unroll
            for (int l = 0; l < 4; l++) acc[i][j][l] = 0.f;

    for (int k0 = 0; k0 < 2*DD; k0 += TBK) {
        const int half = (k0 >= DD);
        const int kkbase = k0 & (DD-1);
        #pragma unroll
        for (int l = 0; l < 2; l++) {
            int q = tid + l * 256;
            int row = q >> 2, kc = (q & 3) << 2;
            int sym = half ? entS[row] : relS[row];
            float4 v = *(const float4*)(tab + (size_t)sym * DD + kkbase + kc);
            float h, lo;
            split2(v.x, h, lo); Ah[kc+0][row] = h; Al[kc+0][row] = lo;
            split2(v.y, h, lo); Ah[kc+1][row] = h; Al[kc+1][row] = lo;
            split2(v.z, h, lo); Ah[kc+2][row] = h; Al[kc+2][row] = lo;
            split2(v.w, h, lo); Ah[kc+3][row] = h; Al[kc+3][row] = lo;
        }
        #pragma unroll
        for (int l = 0; l < 2; l++) {
            int q = tid + l * 256;
            int row = q >> 2, kc = (q & 3) << 2;
            float4 v = *(const float4*)(Wt + (size_t)row * (2*DD) + k0 + kc);
            float h, lo;
            split2(v.x, h, lo); Bh[kc+0][row] = h; Bl[kc+0][row] = lo;
            split2(v.y, h, lo); Bh[kc+1][row] = h; Bl[kc+1][row] = lo;
            split2(v.z, h, lo); Bh[kc+2][row] = h; Bl[kc+2][row] = lo;
            split2(v.w, h, lo); Bh[kc+3][row] = h; Bl[kc+3][row] = lo;
        }
        __syncthreads();
        #pragma unroll
        for (int k8 = 0; k8 < 2; k8++) {
            const int kk = k8 * 8 + (lane & 3);
            uint32_t ah[4][4], al[4][4], bh[4][2], bl[4][2];
            #pragma unroll
            for (int mt = 0; mt < 4; mt++) {
                int m0 = wm * 64 + mt * 16 + (lane >> 2);
                ah[mt][0] = __float_as_uint(Ah[kk][m0]);
                ah[mt][1] = __float_as_uint(Ah[kk][m0+8]);
                ah[mt][2] = __float_as_uint(Ah[kk+4][m0]);
                ah[mt][3] = __float_as_uint(Ah[kk+4][m0+8]);
                al[mt][0] = __float_as_uint(Al[kk][m0]);
                al[mt][1] = __float_as_uint(Al[kk][m0+8]);
                al[mt][2] = __float_as_uint(Al[kk+4][m0]);
                al[mt][3] = __float_as_uint(Al[kk+4][m0+8]);
            }
            #pragma unroll
            for (int nt = 0; nt < 4; nt++) {
                int n0 = wn * 32 + nt * 8 + (lane >> 2);
                bh[nt][0] = __float_as_uint(Bh[kk][n0]);
                bh[nt][1] = __float_as_uint(Bh[kk+4][n0]);
                bl[nt][0] = __float_as_uint(Bl[kk][n0]);
                bl[nt][1] = __float_as_uint(Bl[kk+4][n0]);
            }
            #pragma unroll
            for (int mt = 0; mt < 4; mt++)
                #pragma unroll
                for (int nt = 0; nt < 4; nt++) {
                    mma8(acc[mt][nt], ah[mt], bh[nt]);
                    mma8(acc[mt][nt], ah[mt], bl[nt]);
                    mma8(acc[mt][nt], al[mt], bh[nt]);
                }
        }
        __syncthreads();
    }
    // epilogue: logit = ub + sum_col u[col]*tanh(acc + Wb[col])
    #pragma unroll
    for (int mt = 0; mt < 4; mt++) {
        float pLo = 0.f, pHi = 0.f;
        #pragma unroll
        for (int nt = 0; nt < 4; nt++) {
            int c0 = wn * 32 + nt * 8 + ((lane & 3) << 1);
            pLo += sU[c0]   * tanhf(acc[mt][nt][0] + sB[c0]);
            pLo += sU[c0+1] * tanhf(acc[mt][nt][1] + sB[c0+1]);
            pHi += sU[c0]   * tanhf(acc[mt][nt][2] + sB[c0]);
            pHi += sU[c0+1] * tanhf(acc[mt][nt][3] + sB[c0+1]);
        }
        pLo += __shfl_xor_sync(~0u, pLo, 1); pLo += __shfl_xor_sync(~0u, pLo, 2);
        pHi += __shfl_xor_sync(~0u, pHi, 1); pHi += __shfl_xor_sync(~0u, pHi, 2);
        if ((lane & 3) == 0) {
            int rl = wm * 64 + mt * 16 + (lane >> 2);
            sred[wn][rl]   = pLo;
            sred[wn][rl+8] = pHi;
        }
    }
    __syncthreads();
    if (tid < 128) {
        int row = bm + tid;
        if (row < R_TOT) {
            float s = sred[0][tid] + sred[1][tid] + sred[2][tid] + sred[3][tid];
            g_logits[(size_t)path * R_TOT + row] = s + ub;
        }
    }
}

// ---------------- small GEMM (warp per output), for M=10 support matrices -------
__global__ __launch_bounds__(256) void small_gemm(
    int M, int N, int K,
    const float* __restrict__ A, int lda,
    const float* __restrict__ W, int ldw,
    const float* __restrict__ bias,
    float* __restrict__ C, int ldc,
    int epi, const float* __restrict__ res, int ldres)
{
    int w = (blockIdx.x * 256 + threadIdx.x) >> 5;
    int lane = threadIdx.x & 31;
    if (w >= M * N) return;
    int m = w / N, n = w % N;
    float p = 0.f;
    for (int k = lane; k < K; k += 32) p += A[(size_t)m*lda + k] * W[(size_t)n*ldw + k];
    #pragma unroll
    for (int o = 16; o; o >>= 1) p += __shfl_xor_sync(~0u, p, o);
    if (lane == 0) {
        if (bias) p += bias[n];
        if (epi == 1) p = fmaxf(p, 0.f);
        else if (epi == 2) p += res[(size_t)m*ldres + n];
        C[(size_t)m*ldc + n] = p;
    }
}

// ---------------- softmax over 30 neighbors + weighted pool + tanh --------------
__global__ __launch_bounds__(128) void pool_kernel(
    const float* __restrict__ emb,
    const int* __restrict__ ql, const int* __restrict__ qr,
    const int* __restrict__ sl, const int* __restrict__ sr)
{
    const int gs = blockIdx.x;
    const int tid = threadIdx.x;
    __shared__ float att[2][NBR];
    __shared__ int entS[NBR];
    int set, local;
    if (gs < NQ)            { set=0; local=gs; }
    else if (gs < 2*NQ)     { set=1; local=gs-NQ; }
    else if (gs < 2*NQ+FEWN){ set=2; local=gs-2*NQ; }
    else                    { set=3; local=gs-2*NQ-FEWN; }
    const int rowbase = (set==0?0: set==1?RQ : set==2?2*RQ : 2*RQ+RS) + local*NBR;
    const int* conn = set==0?ql : set==1?qr : set==2?sl : sr;
    const int warp = tid >> 5, lane = tid & 31;

    if (warp == 0 && lane < NBR) entS[lane] = conn[(local*NBR+lane)*2+1];
    if (warp < 2) {
        float v = (lane < NBR) ? g_logits[(size_t)warp*R_TOT + rowbase + lane] : -1e30f;
        float m = v;
        #pragma unroll
        for (int o = 16; o; o >>= 1) m = fmaxf(m, __shfl_xor_sync(~0u, m, o));
        float e = (lane < NBR) ? expf(v - m) : 0.f;
        float s = e;
        #pragma unroll
        for (int o = 16; o; o >>= 1) s += __shfl_xor_sync(~0u, s, o);
        if (lane < NBR) att[warp][lane] = e / s;
    }
    __syncthreads();
    const int d = tid;
    float a0 = 0.f, a1 = 0.f;
    #pragma unroll 6
    for (int nb = 0; nb < NBR; nb++) {
        float ev = emb[(size_t)entS[nb]*DD + d];
        a0 += att[0][nb]*ev;
        a1 += att[1][nb]*ev;
    }
    float t0 = tanhf(a0), t1 = tanhf(a1);
    if (set < 2) {
        g_query[((size_t)0*NQ + local)*H2 + set*DD + d] = t0;
        g_query[((size_t)NQ + local)*H2 + set*DD + d]   = t1;
    } else {
        int s2 = set - 2;
        g_support[(0*FEWN + local)*H2 + s2*DD + d] = t0;
        g_support[(1*FEWN + local)*H2 + s2*DD + d] = t1;
    }
}

// ---------------- layernorm (ddof=1, eps added to sigma) ------------------------
__global__ __launch_bounds__(256) void ln_kernel(
    const float* __restrict__ Z, float* __restrict__ O,
    const float* __restrict__ ga, const float* __restrict__ gb)
{
    const int row = blockIdx.x, c = threadIdx.x;
    float z = Z[(size_t)row*H2 + c];
    __shared__ float s1[H2], s2[H2];
    s1[c] = z; s2[c] = z*z;
    __syncthreads();
    for (int o = 128; o; o >>= 1) {
        if (c < o) { s1[c] += s1[c+o]; s2[c] += s2[c+o]; }
        __syncthreads();
    }
    float mu  = s1[0] * (1.f/H2);
    float var = (s2[0] - (float)H2*mu*mu) * (1.f/(H2-1));
    float sig = sqrtf(fmaxf(var, 0.f));
    O[(size_t)row*H2 + c] = (z - mu)/(sig + 1e-3f)*ga[c] + gb[c];
}

__global__ void smean_kernel() {
    int p = blockIdx.x, c = threadIdx.x;
    float s = 0.f;
    #pragma unroll
    for (int f = 0; f < FEWN; f++) s += g_sg[(p*FEWN + f)*H2 + c];
    g_smean[p*H2 + c] = s * (1.f/FEWN);
}

__global__ void bsum_kernel(const float* __restrict__ bih, const float* __restrict__ bhh) {
    int i = blockIdx.x*blockDim.x + threadIdx.x;
    if (i < NG) g_bsum[i] = bih[i] + bhh[i];
}

// ---------------- LSTM elementwise step (+ rank-5 attn@SW fold) -----------------
__global__ __launch_bounds__(256) void lstm_ew_kernel(int t)
{
    int idx = blockIdx.x*256 + threadIdx.x;     // 0 .. MB*H4-1
    int r = idx >> 9, u = idx & 511;
    size_t base = (size_t)r*NG;
    float gi = g_Gx[base+u],      gf = g_Gx[base+512+u];
    float gg = g_Gx[base+1024+u], go = g_Gx[base+1536+u];
    float cprev = 0.f;
    if (t > 0) {
        gi += g_Ds[base+u];      gf += g_Ds[base+512+u];
        gg += g_Ds[base+1024+u]; go += g_Ds[base+1536+u];
        const float* SW = g_SW + (size_t)(r >> 12) * FEWN * NG;
        #pragma unroll
        for (int f = 0; f < FEWN; f++) {
            float a = g_attn[r*FEWN + f];
            gi += a*SW[f*NG + u];
            gf += a*SW[f*NG + 512 + u];
            gg += a*SW[f*NG + 1024 + u];
            go += a*SW[f*NG + 1536 + u];
        }
        cprev = g_c[(size_t)r*H4 + u];
    }
    float cn = sigm(gf)*cprev + sigm(gi)*tanhf(gg);
    g_c[(size_t)r*H4 + u] = cn;
    if (u < H2) {
        float ho = sigm(go)*tanhf(cn);
        g_h[(size_t)r*H2 + u] = g_qg[(size_t)r*H2 + u] + ho;
    }
}

// ---------------- attention over 5 support rows ---------------------------------
__global__ __launch_bounds__(128) void attn_kernel()
{
    int r = blockIdx.x*4 + (threadIdx.x >> 5);
    int lane = threadIdx.x & 31;
    const float* sg = g_sg + (size_t)(r >> 12) * FEWN * H2;
    float sc[FEWN];
    #pragma unroll
    for (int f = 0; f < FEWN; f++) {
        float p = 0.f;
        for (int c = lane; c < H2; c += 32) p += g_h[(size_t)r*H2 + c]*sg[f*H2 + c];
        #pragma unroll
        for (int o = 16; o; o >>= 1) p += __shfl_xor_sync(~0u, p, o);
        sc[f] = p;
    }
    float m = sc[0];
    #pragma unroll
    for (int f = 1; f < FEWN; f++) m = fmaxf(m, sc[f]);
    float e[FEWN], s = 0.f;
    #pragma unroll
    for (int f = 0; f < FEWN; f++) { e[f] = expf(sc[f]-m); s += e[f]; }
    if (lane < FEWN) g_attn[r*FEWN + lane] = e[lane]/s;
}

__global__ __launch_bounds__(128) void score_kernel(float* __restrict__ out)
{
    int r = blockIdx.x*4 + (threadIdx.x >> 5);
    int lane = threadIdx.x & 31;
    const float* sm = g_smean + (size_t)(r >> 12) * H2;
    float p = 0.f;
    for (int c = lane; c < H2; c += 32) p += g_h[(size_t)r*H2 + c]*sm[c];
    #pragma unroll
    for (int o = 16; o; o >>= 1) p += __shfl_xor_sync(~0u, p, o);
    if (lane == 0) out[r] = p;
}

// ---------------- host orchestration --------------------------------------------
extern "C" void kernel_launch(void* const* d_in, const int* in_sizes, int n_in,
                              void* d_out, int out_size)
{
    (void)in_sizes; (void)n_in; (void)out_size;
    const float* emb   = (const float*)d_in[0];
    const float* embv  = (const float*)d_in[1];
    const float* nW    = (const float*)d_in[2];
    const float* nWb   = (const float*)d_in[3];
    const float* nu    = (const float*)d_in[4];
    const float* nub   = (const float*)d_in[5];
    const float* nvW   = (const float*)d_in[6];
    const float* nvWb  = (const float*)d_in[7];
    const float* nvu   = (const float*)d_in[8];
    const float* nvub  = (const float*)d_in[9];
    const float* p1W   = (const float*)d_in[10];
    const float* p1b   = (const float*)d_in[11];
    const float* p2W   = (const float*)d_in[12];
    const float* p2b   = (const float*)d_in[13];
    const float* ln_a  = (const float*)d_in[14];
    const float* ln_b  = (const float*)d_in[15];
    const float* Wih   = (const float*)d_in[16];
    const float* Whh   = (const float*)d_in[17];
    const float* bih   = (const float*)d_in[18];
    const float* bhh   = (const float*)d_in[19];
    const int* ql = (const int*)d_in[20];
    const int* qr = (const int*)d_in[21];
    const int* sl = (const int*)d_in[22];
    const int* sr = (const int*)d_in[23];
    float* out = (float*)d_out;

    float *p_query, *p_support, *p_qg, *p_sg, *p_h1, *p_z, *p_sh1, *p_sz,
          *p_Gx, *p_Ds, *p_SW, *p_h, *p_bsum;
    cudaGetSymbolAddress((void**)&p_query,   g_query);
    cudaGetSymbolAddress((void**)&p_support, g_support);
    cudaGetSymbolAddress((void**)&p_qg,      g_qg);
    cudaGetSymbolAddress((void**)&p_sg,      g_sg);
    cudaGetSymbolAddress((void**)&p_h1,      g_h1);
    cudaGetSymbolAddress((void**)&p_z,       g_z);
    cudaGetSymbolAddress((void**)&p_sh1,     g_sh1);
    cudaGetSymbolAddress((void**)&p_sz,      g_sz);
    cudaGetSymbolAddress((void**)&p_Gx,      g_Gx);
    cudaGetSymbolAddress((void**)&p_Ds,      g_Ds);
    cudaGetSymbolAddress((void**)&p_SW,      g_SW);
    cudaGetSymbolAddress((void**)&p_h,       g_h);
    cudaGetSymbolAddress((void**)&p_bsum,    g_bsum);

    bsum_kernel<<<(NG+255)/256, 256>>>(bih, bhh);

    dim3 gN((R_TOT + TBM - 1)/TBM, 2);
    neigh_logit_tc<<<gN, 256>>>(emb, embv, nW, nWb, nu, nub,
                                nvW, nvWb, nvu, nvub, ql, qr, sl, sr);
    pool_kernel<<<2*NQ + 2*FEWN, 128>>>(emb, ql, qr, sl, sr);

    // ---- support encoder on support rows (both paths merged: M = 10) ----
    {
        int M = 2*FEWN;
        small_gemm<<<(M*H4*32 + 255)/256, 256>>>(M, H4, H2, p_support, H2, p1W, H2,
                                                 p1b, p_sh1, H4, 1, nullptr, 0);
        small_gemm<<<(M*H2*32 + 255)/256, 256>>>(M, H2, H4, p_sh1, H4, p2W, H4,
                                                 p2b, p_sz, H2, 2, p_support, H2);
        ln_kernel<<<M, 256>>>(p_sz, p_sg, ln_a, ln_b);
        small_gemm<<<(M*NG*32 + 255)/256, 256>>>(M, NG, H2, p_sg, H2, Whh + 256, H4,
                                                 nullptr, p_SW, NG, 0, nullptr, 0);
        smean_kernel<<<2, 256>>>();
    }

    // ---- support encoder on queries (both paths merged: M = 8192) ----
    tgemm_tn<<<dim3(MB/TBM, H4/TBN), 256>>>(MB, H4, H2, p_query, H2, p1W, H2, p1b,
                                            p_h1, H4, 1, nullptr, 0);
    tgemm_tn<<<dim3(MB/TBM, H2/TBN), 256>>>(MB, H2, H4, p_h1, H4, p2W, H4, p2b,
                                            p_z, H2, 2, p_query, H2);
    ln_kernel<<<MB, 256>>>(p_z, p_qg, ln_a, ln_b);

    // ---- G_x = q_g @ Wih^T + (bih+bhh) ----
    tgemm_tn<<<dim3(MB/TBM, NG/TBN), 256>>>(MB, NG, H2, p_qg, H2, Wih, H2,
                                            p_bsum, p_Gx, NG, 0, nullptr, 0);

    // ---- LSTM steps (both paths merged) ----
    lstm_ew_kernel<<<MB*H4/256, 256>>>(0);
    attn_kernel<<<MB/4, 128>>>();
    for (int t = 1; t < 4; t++) {
        tgemm_tn<<<dim3(MB/TBM, NG/TBN), 256>>>(MB, NG, H2, p_h, H2, Whh, H4,
                                                nullptr, p_Ds, NG, 0, nullptr, 0);
        lstm_ew_kernel<<<MB*H4/256, 256>>>(t);
        if (t < 3) attn_kernel<<<MB/4, 128>>>();
    }
    score_kernel<<<MB/4, 128>>>(out);
}

// round 8
// speedup vs baseline: 2.4003x; 1.9824x over previous
#include <cuda_runtime.h>
#include <cuda_bf16.h>
#include <math.h>
#include <stdint.h>

#define DD   128
#define NBR  30
#define NQ   4096
#define FEWN 5
#define H2   256
#define H4   512
#define NG   2048
#define RQ   (NQ*NBR)
#define RS   (FEWN*NBR)
#define R_TOT (2*RQ + 2*RS)
#define MB   (2*NQ)

// ---------------- scratch ----------------
__device__ float g_logits[2*R_TOT];
__device__ float g_query[MB*H2];
__device__ float g_support[2*FEWN*H2];
__device__ float g_qg[MB*H2];
__device__ float g_sg[2*FEWN*H2];
__device__ float g_h1[(size_t)MB*H4];
__device__ float g_z[MB*H2];
__device__ float g_sh1[2*FEWN*H4];
__device__ float g_sz[2*FEWN*H2];
__device__ float g_Gx[(size_t)MB*NG];
__device__ float g_Ds[(size_t)MB*NG];
__device__ float g_SW[2*FEWN*NG];
__device__ float g_smean[2*H2];
__device__ float g_c[(size_t)MB*H4];
__device__ float g_h[MB*H2];
__device__ float g_attn[MB*FEWN];
__device__ float g_bsum[NG];

__device__ __forceinline__ float sigm(float x) { return 1.f/(1.f+expf(-x)); }

__device__ __forceinline__ uint32_t smem_u32(const void* p) {
    uint32_t a;
    asm("{ .reg .u64 t; cvta.to.shared.u64 t, %1; cvt.u32.u64 %0, t; }" : "=r"(a) : "l"(p));
    return a;
}

// ---------------- bf16 mma helpers ----------------
__device__ __forceinline__ void mma_bf16(float* c, const uint32_t* a, const uint32_t* b) {
    asm volatile("mma.sync.aligned.m16n8k16.row.col.f32.bf16.bf16.f32 "
        "{%0,%1,%2,%3}, {%4,%5,%6,%7}, {%8,%9}, {%0,%1,%2,%3};"
        : "+f"(c[0]), "+f"(c[1]), "+f"(c[2]), "+f"(c[3])
        : "r"(a[0]), "r"(a[1]), "r"(a[2]), "r"(a[3]), "r"(b[0]), "r"(b[1]));
}
__device__ __forceinline__ void ldm_x4(uint32_t* r, uint32_t addr) {
    asm volatile("ldmatrix.sync.aligned.m8n8.x4.shared.b16 {%0,%1,%2,%3}, [%4];"
        : "=r"(r[0]), "=r"(r[1]), "=r"(r[2]), "=r"(r[3]) : "r"(addr));
}
__device__ __forceinline__ void ldm_x2(uint32_t* r, uint32_t addr) {
    asm volatile("ldmatrix.sync.aligned.m8n8.x2.shared.b16 {%0,%1}, [%2];"
        : "=r"(r[0]), "=r"(r[1]) : "r"(addr));
}

// convert float4 -> hi/lo bf16 quads, store to smem (8-byte stores)
__device__ __forceinline__ void cvt_store(float4 v, uint16_t* hb, uint16_t* lb, int idx) {
    __nv_bfloat16 h0 = __float2bfloat16(v.x), h1 = __float2bfloat16(v.y);
    __nv_bfloat16 h2 = __float2bfloat16(v.z), h3 = __float2bfloat16(v.w);
    uint32_t p0 = ((uint32_t)__bfloat16_as_ushort(h1) << 16) | __bfloat16_as_ushort(h0);
    uint32_t p1 = ((uint32_t)__bfloat16_as_ushort(h3) << 16) | __bfloat16_as_ushort(h2);
    *(uint2*)(hb + idx) = make_uint2(p0, p1);
    __nv_bfloat16 l0 = __float2bfloat16(v.x - __bfloat162float(h0));
    __nv_bfloat16 l1 = __float2bfloat16(v.y - __bfloat162float(h1));
    __nv_bfloat16 l2 = __float2bfloat16(v.z - __bfloat162float(h2));
    __nv_bfloat16 l3 = __float2bfloat16(v.w - __bfloat162float(h3));
    uint32_t q0 = ((uint32_t)__bfloat16_as_ushort(l1) << 16) | __bfloat16_as_ushort(l0);
    uint32_t q1 = ((uint32_t)__bfloat16_as_ushort(l3) << 16) | __bfloat16_as_ushort(l2);
    *(uint2*)(lb + idx) = make_uint2(q0, q1);
}

#define ASTR 40     // bf16 elements per smem row (32 data + 8 pad; conflict-free ldmatrix)
#define BK 32

// ============ bf16x2 TN GEMM: C = A[M,K] @ W[N,K]^T (+bias/epi) ============
// grid (M/128, N/128), 256 thr. epi: 0 none, 1 relu, 2 +res
__global__ __launch_bounds__(256, 2) void tgemm(
    int M, int N, int K,
    const float* __restrict__ A, int lda,
    const float* __restrict__ W, int ldw,
    const float* __restrict__ bias,
    float* __restrict__ C, int ldc,
    int epi, const float* __restrict__ res, int ldres)
{
    __shared__ uint16_t Ah[128*ASTR], Al[128*ASTR], Bh[128*ASTR], Bl[128*ASTR];
    const int tid = threadIdx.x, lane = tid & 31, wid = tid >> 5;
    const int wm = wid >> 2, wn = wid & 3;            // warp tile 64x32
    const int bm = blockIdx.x * 128, bn = blockIdx.y * 128;

    float acc[4][4][4];
    #pragma unroll
    for (int i = 0; i < 4; i++)
        #pragma unroll
        for (int j = 0; j < 4; j++)
            #pragma unroll
            for (int l = 0; l < 4; l++) acc[i][j][l] = 0.f;

    const uint32_t abh = smem_u32(Ah), abl = smem_u32(Al);
    const uint32_t bbh = smem_u32(Bh), bbl = smem_u32(Bl);
    // lane-resident ldmatrix offsets (bytes)
    const int m_off = wm*64 + (lane & 7) + ((lane >> 3) & 1) * 8;
    const int ka    = (lane >> 4) * 8;
    const uint32_t aoff = (uint32_t)(m_off * ASTR + ka) * 2;
    const int n_off = wn*32 + (lane & 7);
    const int kb    = ((lane >> 3) & 1) * 8;
    const uint32_t boff = (uint32_t)(n_off * ASTR + kb) * 2;

    const int nkt = K >> 5;
    for (int kt = 0; kt < nkt; kt++) {
        const int k0 = kt << 5;
        #pragma unroll
        for (int l = 0; l < 4; l++) {
            int j = tid + l*256;                 // 1024 float4 jobs per matrix
            int row = j >> 3, c4 = (j & 7) << 2;
            float4 va = *(const float4*)(A + (size_t)(bm + row)*lda + k0 + c4);
            cvt_store(va, Ah, Al, row*ASTR + c4);
            float4 vb = *(const float4*)(W + (size_t)(bn + row)*ldw + k0 + c4);
            cvt_store(vb, Bh, Bl, row*ASTR + c4);
        }
        __syncthreads();
        #pragma unroll
        for (int ks = 0; ks < 2; ks++) {
            const uint32_t kso = (uint32_t)(ks * 16) * 2;
            uint32_t bh[4][2], bl[4][2];
            #pragma unroll
            for (int nt = 0; nt < 4; nt++) {
                uint32_t ad = boff + kso + (uint32_t)(nt * 8 * ASTR) * 2;
                ldm_x2(bh[nt], bbh + ad);
                ldm_x2(bl[nt], bbl + ad);
            }
            #pragma unroll
            for (int mt = 0; mt < 4; mt++) {
                uint32_t ad = aoff + kso + (uint32_t)(mt * 16 * ASTR) * 2;
                uint32_t ah[4], al[4];
                ldm_x4(ah, abh + ad);
                ldm_x4(al, abl + ad);
                #pragma unroll
                for (int nt = 0; nt < 4; nt++) {
                    mma_bf16(acc[mt][nt], ah, bh[nt]);
                    mma_bf16(acc[mt][nt], ah, bl[nt]);
                    mma_bf16(acc[mt][nt], al, bh[nt]);
                }
            }
        }
        __syncthreads();
    }
    // epilogue
    #pragma unroll
    for (int mt = 0; mt < 4; mt++) {
        int rlo = bm + wm*64 + mt*16 + (lane >> 2);
        #pragma unroll
        for (int nt = 0; nt < 4; nt++) {
            int col = bn + wn*32 + nt*8 + ((lane & 3) << 1);
            #pragma unroll
            for (int hf = 0; hf < 2; hf++) {
                int row = rlo + hf*8;
                float2 v = make_float2(acc[mt][nt][hf*2], acc[mt][nt][hf*2+1]);
                if (bias) { v.x += bias[col]; v.y += bias[col+1]; }
                if (epi == 1) { v.x = fmaxf(v.x, 0.f); v.y = fmaxf(v.y, 0.f); }
                else if (epi == 2) {
                    float2 rv = *(const float2*)(res + (size_t)row*ldres + col);
                    v.x += rv.x; v.y += rv.y;
                }
                *(float2*)(C + (size_t)row*ldc + col) = v;
            }
        }
    }
}

// ============ neighbor logits: gathered bf16x2 GEMM + tanh/dot epilogue ============
__global__ __launch_bounds__(256, 2) void neigh_tc(
    const float* __restrict__ emb, const float* __restrict__ embv,
    const float* __restrict__ nW,  const float* __restrict__ nWb,
    const float* __restrict__ nu,  const float* __restrict__ nub,
    const float* __restrict__ nvW, const float* __restrict__ nvWb,
    const float* __restrict__ nvu, const float* __restrict__ nvub,
    const int* __restrict__ ql, const int* __restrict__ qr,
    const int* __restrict__ sl, const int* __restrict__ sr)
{
    __shared__ uint16_t Ah[128*ASTR], Al[128*ASTR], Bh[128*ASTR], Bl[128*ASTR];
    __shared__ int relS[128], entS[128];
    __shared__ float sU[128], sB[128];
    __shared__ float sred[4][128];

    const int path = blockIdx.y;
    const float* tab = path ? embv : emb;
    const float* Wt  = path ? nvW  : nW;
    const float* Wb  = path ? nvWb : nWb;
    const float* uu  = path ? nvu  : nu;
    const float  ub  = path ? nvub[0] : nub[0];

    const int tid = threadIdx.x, lane = tid & 31, wid = tid >> 5;
    const int wm = wid >> 2, wn = wid & 3;
    const int bm = blockIdx.x * 128;

    if (tid < 128) {
        int r = bm + tid;
        int rel = 0, ent = 0;
        if (r < R_TOT) {
            const int* conn; int local;
            if (r < RQ)            { conn = ql; local = r; }
            else if (r < 2*RQ)     { conn = qr; local = r - RQ; }
            else if (r < 2*RQ+RS)  { conn = sl; local = r - 2*RQ; }
            else                   { conn = sr; local = r - 2*RQ - RS; }
            rel = conn[local*2]; ent = conn[local*2+1];
        }
        relS[tid] = rel; entS[tid] = ent;
        sU[tid] = uu[tid]; sB[tid] = Wb[tid];
    }
    __syncthreads();

    float acc[4][4][4];
    #pragma unroll
    for (int i = 0; i < 4; i++)
        #pragma unroll
        for (int j = 0; j < 4; j++)
            #pragma unroll
            for (int l = 0; l < 4; l++) acc[i][j][l] = 0.f;

    const uint32_t abh = smem_u32(Ah), abl = smem_u32(Al);
    const uint32_t bbh = smem_u32(Bh), bbl = smem_u32(Bl);
    const int m_off = wm*64 + (lane & 7) + ((lane >> 3) & 1) * 8;
    const int ka    = (lane >> 4) * 8;
    const uint32_t aoff = (uint32_t)(m_off * ASTR + ka) * 2;
    const int n_off = wn*32 + (lane & 7);
    const int kb    = ((lane >> 3) & 1) * 8;
    const uint32_t boff = (uint32_t)(n_off * ASTR + kb) * 2;

    for (int kt = 0; kt < 8; kt++) {               // K = 256
        const int half = kt >> 2;
        const int koff = (kt & 3) << 5;
        #pragma unroll
        for (int l = 0; l < 4; l++) {
            int j = tid + l*256;
            int row = j >> 3, c4 = (j & 7) << 2;
            int sym = half ? entS[row] : relS[row];
            float4 va = *(const float4*)(tab + (size_t)sym*DD + koff + c4);
            cvt_store(va, Ah, Al, row*ASTR + c4);
            float4 vb = *(const float4*)(Wt + (size_t)row*(2*DD) + (kt << 5) + c4);
            cvt_store(vb, Bh, Bl, row*ASTR + c4);
        }
        __syncthreads();
        #pragma unroll
        for (int ks = 0; ks < 2; ks++) {
            const uint32_t kso = (uint32_t)(ks * 16) * 2;
            uint32_t bh[4][2], bl[4][2];
            #pragma unroll
            for (int nt = 0; nt < 4; nt++) {
                uint32_t ad = boff + kso + (uint32_t)(nt * 8 * ASTR) * 2;
                ldm_x2(bh[nt], bbh + ad);
                ldm_x2(bl[nt], bbl + ad);
            }
            #pragma unroll
            for (int mt = 0; mt < 4; mt++) {
                uint32_t ad = aoff + kso + (uint32_t)(mt * 16 * ASTR) * 2;
                uint32_t ah[4], al[4];
                ldm_x4(ah, abh + ad);
                ldm_x4(al, abl + ad);
                #pragma unroll
                for (int nt = 0; nt < 4; nt++) {
                    mma_bf16(acc[mt][nt], ah, bh[nt]);
                    mma_bf16(acc[mt][nt], ah, bl[nt]);
                    mma_bf16(acc[mt][nt], al, bh[nt]);
                }
            }
        }
        __syncthreads();
    }
    // epilogue: logit = ub + sum_col u[col]*tanh(acc + b[col]); reduce over 128 cols
    #pragma unroll
    for (int mt = 0; mt < 4; mt++) {
        float pLo = 0.f, pHi = 0.f;
        #pragma unroll
        for (int nt = 0; nt < 4; nt++) {
            int c0 = wn*32 + nt*8 + ((lane & 3) << 1);
            pLo += sU[c0]   * tanhf(acc[mt][nt][0] + sB[c0]);
            pLo += sU[c0+1] * tanhf(acc[mt][nt][1] + sB[c0+1]);
            pHi += sU[c0]   * tanhf(acc[mt][nt][2] + sB[c0]);
            pHi += sU[c0+1] * tanhf(acc[mt][nt][3] + sB[c0+1]);
        }
        pLo += __shfl_xor_sync(~0u, pLo, 1); pLo += __shfl_xor_sync(~0u, pLo, 2);
        pHi += __shfl_xor_sync(~0u, pHi, 1); pHi += __shfl_xor_sync(~0u, pHi, 2);
        if ((lane & 3) == 0) {
            int rl = wm*64 + mt*16 + (lane >> 2);
            sred[wn][rl]   = pLo;
            sred[wn][rl+8] = pHi;
        }
    }
    __syncthreads();
    if (tid < 128) {
        int row = bm + tid;
        if (row < R_TOT) {
            float s = sred[0][tid] + sred[1][tid] + sred[2][tid] + sred[3][tid];
            g_logits[(size_t)path*R_TOT + row] = s + ub;
        }
    }
}

// ---------------- small GEMM (warp per output) ----------------------------------
__global__ __launch_bounds__(256) void small_gemm(
    int M, int N, int K,
    const float* __restrict__ A, int lda,
    const float* __restrict__ W, int ldw,
    const float* __restrict__ bias,
    float* __restrict__ C, int ldc,
    int epi, const float* __restrict__ res, int ldres)
{
    int w = (blockIdx.x * 256 + threadIdx.x) >> 5;
    int lane = threadIdx.x & 31;
    if (w >= M * N) return;
    int m = w / N, n = w % N;
    float p = 0.f;
    for (int k = lane; k < K; k += 32) p += A[(size_t)m*lda + k] * W[(size_t)n*ldw + k];
    #pragma unroll
    for (int o = 16; o; o >>= 1) p += __shfl_xor_sync(~0u, p, o);
    if (lane == 0) {
        if (bias) p += bias[n];
        if (epi == 1) p = fmaxf(p, 0.f);
        else if (epi == 2) p += res[(size_t)m*ldres + n];
        C[(size_t)m*ldc + n] = p;
    }
}

// ---------------- softmax over 30 neighbors + weighted pool + tanh --------------
__global__ __launch_bounds__(128) void pool_kernel(
    const float* __restrict__ emb,
    const int* __restrict__ ql, const int* __restrict__ qr,
    const int* __restrict__ sl, const int* __restrict__ sr)
{
    const int gs = blockIdx.x;
    const int tid = threadIdx.x;
    __shared__ float att[2][NBR];
    __shared__ int entS[NBR];
    int set, local;
    if (gs < NQ)            { set=0; local=gs; }
    else if (gs < 2*NQ)     { set=1; local=gs-NQ; }
    else if (gs < 2*NQ+FEWN){ set=2; local=gs-2*NQ; }
    else                    { set=3; local=gs-2*NQ-FEWN; }
    const int rowbase = (set==0?0: set==1?RQ : set==2?2*RQ : 2*RQ+RS) + local*NBR;
    const int* conn = set==0?ql : set==1?qr : set==2?sl : sr;
    const int warp = tid >> 5, lane = tid & 31;

    if (warp == 0 && lane < NBR) entS[lane] = conn[(local*NBR+lane)*2+1];
    if (warp < 2) {
        float v = (lane < NBR) ? g_logits[(size_t)warp*R_TOT + rowbase + lane] : -1e30f;
        float m = v;
        #pragma unroll
        for (int o = 16; o; o >>= 1) m = fmaxf(m, __shfl_xor_sync(~0u, m, o));
        float e = (lane < NBR) ? expf(v - m) : 0.f;
        float s = e;
        #pragma unroll
        for (int o = 16; o; o >>= 1) s += __shfl_xor_sync(~0u, s, o);
        if (lane < NBR) att[warp][lane] = e / s;
    }
    __syncthreads();
    const int d = tid;
    float a0 = 0.f, a1 = 0.f;
    #pragma unroll 6
    for (int nb = 0; nb < NBR; nb++) {
        float ev = emb[(size_t)entS[nb]*DD + d];
        a0 += att[0][nb]*ev;
        a1 += att[1][nb]*ev;
    }
    float t0 = tanhf(a0), t1 = tanhf(a1);
    if (set < 2) {
        g_query[((size_t)0*NQ + local)*H2 + set*DD + d] = t0;
        g_query[((size_t)NQ + local)*H2 + set*DD + d]   = t1;
    } else {
        int s2 = set - 2;
        g_support[(0*FEWN + local)*H2 + s2*DD + d] = t0;
        g_support[(1*FEWN + local)*H2 + s2*DD + d] = t1;
    }
}

// ---------------- layernorm (ddof=1, eps added to sigma) ------------------------
__global__ __launch_bounds__(256) void ln_kernel(
    const float* __restrict__ Z, float* __restrict__ O,
    const float* __restrict__ ga, const float* __restrict__ gb)
{
    const int row = blockIdx.x, c = threadIdx.x;
    float z = Z[(size_t)row*H2 + c];
    __shared__ float s1[H2], s2[H2];
    s1[c] = z; s2[c] = z*z;
    __syncthreads();
    for (int o = 128; o; o >>= 1) {
        if (c < o) { s1[c] += s1[c+o]; s2[c] += s2[c+o]; }
        __syncthreads();
    }
    float mu  = s1[0] * (1.f/H2);
    float var = (s2[0] - (float)H2*mu*mu) * (1.f/(H2-1));
    float sig = sqrtf(fmaxf(var, 0.f));
    O[(size_t)row*H2 + c] = (z - mu)/(sig + 1e-3f)*ga[c] + gb[c];
}

__global__ void smean_kernel() {
    int p = blockIdx.x, c = threadIdx.x;
    float s = 0.f;
    #pragma unroll
    for (int f = 0; f < FEWN; f++) s += g_sg[(p*FEWN + f)*H2 + c];
    g_smean[p*H2 + c] = s * (1.f/FEWN);
}

__global__ void bsum_kernel(const float* __restrict__ bih, const float* __restrict__ bhh) {
    int i = blockIdx.x*blockDim.x + threadIdx.x;
    if (i < NG) g_bsum[i] = bih[i] + bhh[i];
}

// ---------------- LSTM elementwise step (+ rank-5 attn@SW fold) -----------------
__global__ __launch_bounds__(256) void lstm_ew_kernel(int t)
{
    int idx = blockIdx.x*256 + threadIdx.x;
    int r = idx >> 9, u = idx & 511;
    const float* G = (t > 0) ? g_Ds : g_Gx;
    size_t base = (size_t)r*NG;
    float gi = G[base+u],      gf = G[base+512+u];
    float gg = G[base+1024+u], go = G[base+1536+u];
    float cprev = 0.f;
    if (t > 0) {
        const float* SW = g_SW + (size_t)(r >> 12) * FEWN * NG;
        #pragma unroll
        for (int f = 0; f < FEWN; f++) {
            float a = g_attn[r*FEWN + f];
            gi += a*SW[f*NG + u];
            gf += a*SW[f*NG + 512 + u];
            gg += a*SW[f*NG + 1024 + u];
            go += a*SW[f*NG + 1536 + u];
        }
        cprev = g_c[(size_t)r*H4 + u];
    }
    float cn = sigm(gf)*cprev + sigm(gi)*tanhf(gg);
    g_c[(size_t)r*H4 + u] = cn;
    if (u < H2) {
        float ho = sigm(go)*tanhf(cn);
        g_h[(size_t)r*H2 + u] = g_qg[(size_t)r*H2 + u] + ho;
    }
}

// ---------------- attention over 5 support rows ---------------------------------
__global__ __launch_bounds__(128) void attn_kernel()
{
    int r = blockIdx.x*4 + (threadIdx.x >> 5);
    int lane = threadIdx.x & 31;
    const float* sg = g_sg + (size_t)(r >> 12) * FEWN * H2;
    float sc[FEWN];
    #pragma unroll
    for (int f = 0; f < FEWN; f++) {
        float p = 0.f;
        for (int c = lane; c < H2; c += 32) p += g_h[(size_t)r*H2 + c]*sg[f*H2 + c];
        #pragma unroll
        for (int o = 16; o; o >>= 1) p += __shfl_xor_sync(~0u, p, o);
        sc[f] = p;
    }
    float m = sc[0];
    #pragma unroll
    for (int f = 1; f < FEWN; f++) m = fmaxf(m, sc[f]);
    float e[FEWN], s = 0.f;
    #pragma unroll
    for (int f = 0; f < FEWN; f++) { e[f] = expf(sc[f]-m); s += e[f]; }
    if (lane < FEWN) g_attn[r*FEWN + lane] = e[lane]/s;
}

__global__ __launch_bounds__(128) void score_kernel(float* __restrict__ out)
{
    int r = blockIdx.x*4 + (threadIdx.x >> 5);
    int lane = threadIdx.x & 31;
    const float* sm = g_smean + (size_t)(r >> 12) * H2;
    float p = 0.f;
    for (int c = lane; c < H2; c += 32) p += g_h[(size_t)r*H2 + c]*sm[c];
    #pragma unroll
    for (int o = 16; o; o >>= 1) p += __shfl_xor_sync(~0u, p, o);
    if (lane == 0) out[r] = p;
}

// ---------------- host orchestration --------------------------------------------
extern "C" void kernel_launch(void* const* d_in, const int* in_sizes, int n_in,
                              void* d_out, int out_size)
{
    (void)in_sizes; (void)n_in; (void)out_size;
    const float* emb   = (const float*)d_in[0];
    const float* embv  = (const float*)d_in[1];
    const float* nW    = (const float*)d_in[2];
    const float* nWb   = (const float*)d_in[3];
    const float* nu    = (const float*)d_in[4];
    const float* nub   = (const float*)d_in[5];
    const float* nvW   = (const float*)d_in[6];
    const float* nvWb  = (const float*)d_in[7];
    const float* nvu   = (const float*)d_in[8];
    const float* nvub  = (const float*)d_in[9];
    const float* p1W   = (const float*)d_in[10];
    const float* p1b   = (const float*)d_in[11];
    const float* p2W   = (const float*)d_in[12];
    const float* p2b   = (const float*)d_in[13];
    const float* ln_a  = (const float*)d_in[14];
    const float* ln_b  = (const float*)d_in[15];
    const float* Wih   = (const float*)d_in[16];
    const float* Whh   = (const float*)d_in[17];
    const float* bih   = (const float*)d_in[18];
    const float* bhh   = (const float*)d_in[19];
    const int* ql = (const int*)d_in[20];
    const int* qr = (const int*)d_in[21];
    const int* sl = (const int*)d_in[22];
    const int* sr = (const int*)d_in[23];
    float* out = (float*)d_out;

    float *p_query, *p_support, *p_qg, *p_sg, *p_h1, *p_z, *p_sh1, *p_sz,
          *p_Gx, *p_Ds, *p_SW, *p_h, *p_bsum;
    cudaGetSymbolAddress((void**)&p_query,   g_query);
    cudaGetSymbolAddress((void**)&p_support, g_support);
    cudaGetSymbolAddress((void**)&p_qg,      g_qg);
    cudaGetSymbolAddress((void**)&p_sg,      g_sg);
    cudaGetSymbolAddress((void**)&p_h1,      g_h1);
    cudaGetSymbolAddress((void**)&p_z,       g_z);
    cudaGetSymbolAddress((void**)&p_sh1,     g_sh1);
    cudaGetSymbolAddress((void**)&p_sz,      g_sz);
    cudaGetSymbolAddress((void**)&p_Gx,      g_Gx);
    cudaGetSymbolAddress((void**)&p_Ds,      g_Ds);
    cudaGetSymbolAddress((void**)&p_SW,      g_SW);
    cudaGetSymbolAddress((void**)&p_h,       g_h);
    cudaGetSymbolAddress((void**)&p_bsum,    g_bsum);

    bsum_kernel<<<(NG+255)/256, 256>>>(bih, bhh);

    dim3 gN((R_TOT + 127)/128, 2);
    neigh_tc<<<gN, 256>>>(emb, embv, nW, nWb, nu, nub,
                          nvW, nvWb, nvu, nvub, ql, qr, sl, sr);
    pool_kernel<<<2*NQ + 2*FEWN, 128>>>(emb, ql, qr, sl, sr);

    // ---- support rows (M=10, both paths) ----
    {
        int M = 2*FEWN;
        small_gemm<<<(M*H4*32 + 255)/256, 256>>>(M, H4, H2, p_support, H2, p1W, H2,
                                                 p1b, p_sh1, H4, 1, nullptr, 0);
        small_gemm<<<(M*H2*32 + 255)/256, 256>>>(M, H2, H4, p_sh1, H4, p2W, H4,
                                                 p2b, p_sz, H2, 2, p_support, H2);
        ln_kernel<<<M, 256>>>(p_sz, p_sg, ln_a, ln_b);
        small_gemm<<<(M*NG*32 + 255)/256, 256>>>(M, NG, H2, p_sg, H2, Whh + 256, H4,
                                                 nullptr, p_SW, NG, 0, nullptr, 0);
        smean_kernel<<<2, 256>>>();
    }

    // ---- support encoder on queries (M=8192) ----
    tgemm<<<dim3(MB/128, H4/128), 256>>>(MB, H4, H2, p_query, H2, p1W, H2,
                                         p1b, p_h1, H4, 1, nullptr, 0);
    tgemm<<<dim3(MB/128, H2/128), 256>>>(MB, H2, H4, p_h1, H4, p2W, H4,
                                         p2b, p_z, H2, 2, p_query, H2);
    ln_kernel<<<MB, 256>>>(p_z, p_qg, ln_a, ln_b);

    // ---- G_x = q_g @ Wih^T + (bih+bhh) ----
    tgemm<<<dim3(MB/128, NG/128), 256>>>(MB, NG, H2, p_qg, H2, Wih, H2,
                                         p_bsum, p_Gx, NG, 0, nullptr, 0);

    // ---- LSTM steps ----
    lstm_ew_kernel<<<MB*H4/256, 256>>>(0);
    attn_kernel<<<MB/4, 128>>>();
    for (int t = 1; t < 4; t++) {
        // Ds = h @ WhhA^T + Gx  (residual fused)
        tgemm<<<dim3(MB/128, NG/128), 256>>>(MB, NG, H2, p_h, H2, Whh, H4,
                                             nullptr, p_Ds, NG, 2, p_Gx, NG);
        lstm_ew_kernel<<<MB*H4/256, 256>>>(t);
        if (t < 3) attn_kernel<<<MB/4, 128>>>();
    }
    score_kernel<<<MB/4, 128>>>(out);
}